// round 12
// baseline (speedup 1.0000x reference)
#include <cuda_runtime.h>
#include <cuda_bf16.h>

#define N_EXPERTS 48
#define D_IN 163840            // 2*1280*8*8
#define D_OUT 2
#define BATCH 512
#define THREADS 256
#define G 2                    // samples per group (same expert)
#define MAXG ((BATCH + N_EXPERTS) / G)   // 280 groups worst case
#define NSPLIT 16              // D_IN split
#define CHUNK (D_IN / NSPLIT)  // 10240 floats
#define N4 (CHUNK / 4)         // 2560 float4
#define ITERS (N4 / THREADS)   // 10
#define GRID_MAIN (148 * 6)    // persistent: one resident wave
#define PREP_SEGS 4
#define SEG_LEN (BATCH / PREP_SEGS)  // 128

// ---- scratch (device globals: no allocation allowed) ----
__device__ float g_partials[BATCH * NSPLIT * 2];
__device__ int   g_count[BATCH];   // per-sample split tickets (self-resetting)

__global__ __launch_bounds__(THREADS, 6)
void moe_gemv_persistent(const float* __restrict__ x,
                         const int* __restrict__ t,
                         const float* __restrict__ W,
                         const float* __restrict__ bias,
                         float* __restrict__ out) {
    const int tid  = threadIdx.x;
    const int warp = tid >> 5;
    const int lane = tid & 31;

    // ---------- one-time per-CTA grouping into SMEM ----------
    __shared__ int sh_e[BATCH];
    __shared__ int segbase[N_EXPERTS][PREP_SEGS];
    __shared__ int gb[N_EXPERTS];
    __shared__ int rnk[BATCH];
    __shared__ int sh_gs[MAXG * G];   // group -> sample ids (-1 empty)
    __shared__ int sh_ge[MAXG];       // group -> expert
    __shared__ int sh_ngroups;
    __shared__ float s_red[THREADS / 32][4];

    for (int j = tid; j < BATCH; j += THREADS) {
        int e = t[j] - 1;
        sh_e[j] = ((e % N_EXPERTS) + N_EXPERTS) % N_EXPERTS;
    }
    for (int i = tid; i < MAXG * G; i += THREADS) sh_gs[i] = -1;
    __syncthreads();

    if (tid < N_EXPERTS * PREP_SEGS) {              // per-(expert,segment) counts
        const int ex = tid / PREP_SEGS, seg = tid % PREP_SEGS;
        int c = 0;
        for (int j = seg * SEG_LEN; j < seg * SEG_LEN + SEG_LEN; j++)
            c += (sh_e[j] == ex);
        segbase[ex][seg] = c;
    }
    __syncthreads();
    if (tid < N_EXPERTS) {                          // scan segments -> counts
        int r = 0;
        #pragma unroll
        for (int s = 0; s < PREP_SEGS; s++) {
            int c = segbase[tid][s];
            segbase[tid][s] = r;
            r += c;
        }
        gb[tid] = r;                                // temporarily: count of expert
    }
    __syncthreads();
    if (tid == 0) {                                 // group bases
        int gsum = 0;
        for (int e = 0; e < N_EXPERTS; e++) {
            const int c = gb[e];
            gb[e] = gsum;
            gsum += (c + G - 1) / G;
        }
        sh_ngroups = gsum;
    }
    __syncthreads();
    if (tid < N_EXPERTS * PREP_SEGS) {              // stable ranks
        const int ex = tid / PREP_SEGS, seg = tid % PREP_SEGS;
        int r = segbase[ex][seg];
        for (int j = seg * SEG_LEN; j < seg * SEG_LEN + SEG_LEN; j++)
            if (sh_e[j] == ex) rnk[j] = r++;
    }
    __syncthreads();
    for (int j = tid; j < BATCH; j += THREADS) {    // fill group tables
        const int r = rnk[j], ee = sh_e[j];
        const int grp = gb[ee] + r / G;
        sh_gs[grp * G + (r % G)] = j;
        if ((r % G) == 0) sh_ge[grp] = ee;
    }
    __syncthreads();

    const int total = sh_ngroups * NSPLIT;
    const float4* __restrict__ x4 = reinterpret_cast<const float4*>(x);

    // ---------- persistent tile loop (static stride: deterministic) ----------
    for (int tile = blockIdx.x; tile < total; tile += GRID_MAIN) {
        const int grp   = tile >> 4;                // NSPLIT = 16
        const int split = tile & (NSPLIT - 1);

        const int sA     = sh_gs[grp * G + 0];
        const int sB_raw = sh_gs[grp * G + 1];
        const bool hasB  = (sB_raw >= 0);
        const int sB     = hasB ? sB_raw : sA;
        const int e      = sh_ge[grp];

        const int base4 = split * N4;
        const float4* __restrict__ wv =
            reinterpret_cast<const float4*>(W + (size_t)e * D_IN * D_OUT) + 2 * base4;
        const int xiA = sA * (D_IN / 4) + base4;
        const int xiB = sB * (D_IN / 4) + base4;

        float a0 = 0.0f, a1 = 0.0f, b0 = 0.0f, b1 = 0.0f;

        #pragma unroll
        for (int k = 0; k < ITERS; k++) {
            const int i = tid + k * THREADS;
            const float4 xa = __ldcs(&x4[xiA + i]);   // stream, evict-first
            const float4 xb = __ldcs(&x4[xiB + i]);
            const float4 w0 = __ldg(&wv[2 * i]);      // L1+L2 cached
            const float4 w1 = __ldg(&wv[2 * i + 1]);
            a0 = fmaf(xa.x, w0.x, a0);  a1 = fmaf(xa.x, w0.y, a1);
            b0 = fmaf(xb.x, w0.x, b0);  b1 = fmaf(xb.x, w0.y, b1);
            a0 = fmaf(xa.y, w0.z, a0);  a1 = fmaf(xa.y, w0.w, a1);
            b0 = fmaf(xb.y, w0.z, b0);  b1 = fmaf(xb.y, w0.w, b1);
            a0 = fmaf(xa.z, w1.x, a0);  a1 = fmaf(xa.z, w1.y, a1);
            b0 = fmaf(xb.z, w1.x, b0);  b1 = fmaf(xb.z, w1.y, b1);
            a0 = fmaf(xa.w, w1.z, a0);  a1 = fmaf(xa.w, w1.w, a1);
            b0 = fmaf(xb.w, w1.z, b0);  b1 = fmaf(xb.w, w1.w, b1);
        }

        #pragma unroll
        for (int off = 16; off > 0; off >>= 1) {
            a0 += __shfl_down_sync(0xFFFFFFFFu, a0, off);
            a1 += __shfl_down_sync(0xFFFFFFFFu, a1, off);
            b0 += __shfl_down_sync(0xFFFFFFFFu, b0, off);
            b1 += __shfl_down_sync(0xFFFFFFFFu, b1, off);
        }
        if (lane == 0) {
            s_red[warp][0] = a0; s_red[warp][1] = a1;
            s_red[warp][2] = b0; s_red[warp][3] = b1;
        }
        __syncthreads();

        if (tid == 0) {
            float f[4] = {0.0f, 0.0f, 0.0f, 0.0f};
            #pragma unroll
            for (int w = 0; w < THREADS / 32; w++) {
                f[0] += s_red[w][0]; f[1] += s_red[w][1];
                f[2] += s_red[w][2]; f[3] += s_red[w][3];
            }
            g_partials[(sA * NSPLIT + split) * 2 + 0] = f[0];
            g_partials[(sA * NSPLIT + split) * 2 + 1] = f[1];
            if (hasB) {
                g_partials[(sB * NSPLIT + split) * 2 + 0] = f[2];
                g_partials[(sB * NSPLIT + split) * 2 + 1] = f[3];
            }
            __threadfence();

            // Per-sample ticket; last arriver finishes (fixed-order sum).
            #pragma unroll
            for (int which = 0; which < 2; which++) {
                if (which == 1 && !hasB) break;
                const int s = (which == 0) ? sA : sB;
                int old = atomicAdd(&g_count[s], 1);
                if (old == NSPLIT - 1) {
                    g_count[s] = 0;             // reset for next graph replay
                    __threadfence();
                    volatile const float* p = g_partials + (size_t)s * NSPLIT * 2;
                    float o0 = 0.0f, o1 = 0.0f;
                    #pragma unroll 4
                    for (int sp = 0; sp < NSPLIT; sp++) {
                        o0 += p[2 * sp + 0];
                        o1 += p[2 * sp + 1];
                    }
                    out[2 * s + 0] = o0 + bias[2 * e + 0];
                    out[2 * s + 1] = o1 + bias[2 * e + 1];
                }
            }
        }
        __syncthreads();    // protect s_red reuse next tile
    }
}

extern "C" void kernel_launch(void* const* d_in, const int* in_sizes, int n_in,
                              void* d_out, int out_size) {
    const float* x    = (const float*)d_in[0];  // [512, 2,1280,8,8] fp32
    const int*   t    = (const int*)d_in[1];    // [512] int32
    const float* W    = (const float*)d_in[2];  // [48, 163840, 2] fp32
    const float* bias = (const float*)d_in[3];  // [48, 2] fp32
    float* out = (float*)d_out;                 // [512, 2] fp32

    moe_gemv_persistent<<<GRID_MAIN, THREADS>>>(x, t, W, bias, out);
}

// round 13
// speedup vs baseline: 1.4458x; 1.4458x over previous
#include <cuda_runtime.h>
#include <cuda_bf16.h>

#define N_EXPERTS 48
#define D_IN 163840            // 2*1280*8*8
#define D_OUT 2
#define BATCH 512
#define THREADS 256
#define G 4                    // samples per group (same expert)
#define MAXG (BATCH / G + N_EXPERTS)   // 176 worst case
#define NSPLIT 16              // D_IN split
#define CHUNK (D_IN / NSPLIT)  // 10240 floats
#define N4 (CHUNK / 4)         // 2560 float4
#define ITERS (N4 / THREADS)   // 10
#define GRID_MAIN (MAXG * NSPLIT)   // 2816 CTAs

// ---- scratch (device globals: no allocation allowed) ----
__device__ float g_partials[BATCH * NSPLIT * 2];
__device__ int   g_count[BATCH];   // per-sample split tickets (self-resetting)

__global__ __launch_bounds__(THREADS, 5)
void moe_gemv_g4(const float* __restrict__ x,
                 const int* __restrict__ t,
                 const float* __restrict__ W,
                 const float* __restrict__ bias,
                 float* __restrict__ out) {
    const int grp   = blockIdx.x >> 4;          // NSPLIT = 16
    const int split = blockIdx.x & (NSPLIT - 1);
    const int tid   = threadIdx.x;
    const int warp  = tid >> 5;
    const int lane  = tid & 31;

    // ---------- per-CTA redundant grouping (no inter-CTA sync) ----------
    __shared__ int sh_hist[N_EXPERTS];
    __shared__ int sh_meta[4];        // emy, r0, ngroups, cntE
    __shared__ int sh_wsum[THREADS / 32];
    __shared__ int sh_sel[G];         // samples at ranks r0..r0+G-1

    if (tid < N_EXPERTS) sh_hist[tid] = 0;
    __syncthreads();

    // samples j0 = 2*tid, j1 = 2*tid+1 (contiguous order for stable ranks)
    const int j0 = 2 * tid, j1 = 2 * tid + 1;
    int e0 = t[j0] - 1; e0 = ((e0 % N_EXPERTS) + N_EXPERTS) % N_EXPERTS;
    int e1 = t[j1] - 1; e1 = ((e1 % N_EXPERTS) + N_EXPERTS) % N_EXPERTS;
    atomicAdd(&sh_hist[e0], 1);
    atomicAdd(&sh_hist[e1], 1);
    __syncthreads();

    if (tid == 0) {
        int base = 0, emy = -1, r0 = 0;
        #pragma unroll 4
        for (int e = 0; e < N_EXPERTS; e++) {
            const int c = sh_hist[e];
            const int g = (c + G - 1) / G;
            if (emy < 0 && grp < base + g) { emy = e; r0 = (grp - base) * G; }
            base += g;
        }
        sh_meta[0] = emy;
        sh_meta[1] = r0;
        sh_meta[2] = base;                      // total groups
        sh_meta[3] = (emy >= 0) ? sh_hist[emy] : 0;
    }
    __syncthreads();

    const int ngroups = sh_meta[2];
    if (grp >= ngroups) return;                 // empty group slot
    const int emy  = sh_meta[0];
    const int r0   = sh_meta[1];
    const int cntE = sh_meta[3];

    // locate samples with stable ranks r0..r0+G-1 for expert emy
    {
        const int m0 = (e0 == emy) ? 1 : 0;
        const int m1 = (e1 == emy) ? 1 : 0;
        int v = m0 + m1;                        // pair sum, inclusive scan
        #pragma unroll
        for (int off = 1; off < 32; off <<= 1) {
            int n = __shfl_up_sync(0xFFFFFFFFu, v, off);
            if (lane >= off) v += n;
        }
        if (lane == 31) sh_wsum[warp] = v;
        __syncthreads();
        int wbase = 0;
        #pragma unroll
        for (int w = 0; w < THREADS / 32; w++)
            wbase += (w < warp) ? sh_wsum[w] : 0;
        const int excl0 = wbase + v - (m0 + m1);  // exclusive prefix at j0
        const int excl1 = excl0 + m0;             // exclusive prefix at j1
        const int d0 = excl0 - r0, d1 = excl1 - r0;
        if (m0 && d0 >= 0 && d0 < G) sh_sel[d0] = j0;
        if (m1 && d1 >= 0 && d1 < G) sh_sel[d1] = j1;
        __syncthreads();
    }

    int samp[G];
    unsigned vmask = 0;
    #pragma unroll
    for (int k = 0; k < G; k++) {
        const bool ok = (r0 + k < cntE);
        samp[k] = ok ? sh_sel[k] : sh_sel[0];
        if (ok) vmask |= (1u << k);
    }

    // ---------- grouped split-K mainloop ----------
    const int base4 = split * N4;               // float4 offset in sample row
    const float4* __restrict__ x4 = reinterpret_cast<const float4*>(x);
    const float4* __restrict__ wv =
        reinterpret_cast<const float4*>(W + (size_t)emy * D_IN * D_OUT) + 2 * base4;
    int xi[G];
    #pragma unroll
    for (int k = 0; k < G; k++)
        xi[k] = samp[k] * (D_IN / 4) + base4;

    float acc[2 * G];
    #pragma unroll
    for (int v = 0; v < 2 * G; v++) acc[v] = 0.0f;

    #pragma unroll
    for (int it = 0; it < ITERS; it++) {
        const int i = tid + it * THREADS;
        const float4 w0 = __ldg(&wv[2 * i]);      // dims d,d+1 (both outputs)
        const float4 w1 = __ldg(&wv[2 * i + 1]);  // dims d+2,d+3
        #pragma unroll
        for (int k = 0; k < G; k++) {
            const float4 xq = __ldcs(&x4[xi[k] + i]);   // stream, evict-first
            acc[2 * k + 0] = fmaf(xq.x, w0.x, acc[2 * k + 0]);
            acc[2 * k + 1] = fmaf(xq.x, w0.y, acc[2 * k + 1]);
            acc[2 * k + 0] = fmaf(xq.y, w0.z, acc[2 * k + 0]);
            acc[2 * k + 1] = fmaf(xq.y, w0.w, acc[2 * k + 1]);
            acc[2 * k + 0] = fmaf(xq.z, w1.x, acc[2 * k + 0]);
            acc[2 * k + 1] = fmaf(xq.z, w1.y, acc[2 * k + 1]);
            acc[2 * k + 0] = fmaf(xq.w, w1.z, acc[2 * k + 0]);
            acc[2 * k + 1] = fmaf(xq.w, w1.w, acc[2 * k + 1]);
        }
    }

    // warp reduction of 8 accumulators
    #pragma unroll
    for (int off = 16; off > 0; off >>= 1) {
        #pragma unroll
        for (int v = 0; v < 2 * G; v++)
            acc[v] += __shfl_down_sync(0xFFFFFFFFu, acc[v], off);
    }

    __shared__ float s_red[THREADS / 32][2 * G];
    if (lane == 0) {
        #pragma unroll
        for (int v = 0; v < 2 * G; v++) s_red[warp][v] = acc[v];
    }
    __syncthreads();

    // warp 0, lanes 0..2G-1: one value each across 8 warps
    if (warp == 0 && lane < 2 * G) {
        float f = 0.0f;
        #pragma unroll
        for (int w = 0; w < THREADS / 32; w++) f += s_red[w][lane];
        const int k = lane >> 1, c = lane & 1;
        const int s = samp[k];
        const bool ok = (vmask >> k) & 1u;
        if (ok)
            g_partials[(s * NSPLIT + split) * 2 + c] = f;
        __threadfence();
        // Per-sample ticket (c==0 lane only); last arriver finishes.
        if (ok && c == 0) {
            int old = atomicAdd(&g_count[s], 1);
            if (old == NSPLIT - 1) {
                g_count[s] = 0;                 // reset for next graph replay
                __threadfence();
                volatile const float* p = g_partials + (size_t)s * NSPLIT * 2;
                float o0 = 0.0f, o1 = 0.0f;
                #pragma unroll 4
                for (int sp = 0; sp < NSPLIT; sp++) {
                    o0 += p[2 * sp + 0];
                    o1 += p[2 * sp + 1];
                }
                out[2 * s + 0] = o0 + bias[2 * emy + 0];
                out[2 * s + 1] = o1 + bias[2 * emy + 1];
            }
        }
    }
}

extern "C" void kernel_launch(void* const* d_in, const int* in_sizes, int n_in,
                              void* d_out, int out_size) {
    const float* x    = (const float*)d_in[0];  // [512, 2,1280,8,8] fp32
    const int*   t    = (const int*)d_in[1];    // [512] int32
    const float* W    = (const float*)d_in[2];  // [48, 163840, 2] fp32
    const float* bias = (const float*)d_in[3];  // [48, 2] fp32
    float* out = (float*)d_out;                 // [512, 2] fp32

    moe_gemv_g4<<<GRID_MAIN, THREADS>>>(x, t, W, bias, out);
}